// round 2
// baseline (speedup 1.0000x reference)
#include <cuda_runtime.h>

// ---------------------------------------------------------------------------
// TinyMixedHeteroLinkPredictor
//
// Algebraic restructure: fold the 8->1 scorer into the per-node encoders.
//   logit(e) = x_T(src)[src] . v_{T,src} + x_T(dst)[dst] . v_{T,dst} + c[type]
// Precompute per node n:
//   SA[n] = { author_x[n].v_a_src , paper_x[n].v_p_src }   (float2)
//   SD[n] = { author_x[n].v_a_dst , paper_x[n].v_p_dst }   (float2)
// Edge pass: two random 8B gathers + per-type select + constant.
// ---------------------------------------------------------------------------

#define NMAX 2000000

struct Params {
    float4 va_s, vp_s, va_d, vp_d;
    float  c[4];
    int    fs[4];
    int    fd[4];
};

__device__ Params g_params;
__device__ float2 g_SA[NMAX];
__device__ float2 g_SD[NMAX];

// --- tiny setup: fold Wa/Wp/ba/bp/Ws/bs into 4 vectors + per-type constants ---
__global__ void setup_k(const float* __restrict__ Wa, const float* __restrict__ ba,
                        const float* __restrict__ Wp, const float* __restrict__ bp,
                        const float* __restrict__ Ws, const float* __restrict__ bs,
                        const int* __restrict__ fsrc, const int* __restrict__ fdst)
{
    float vas[4], vps[4], vad[4], vpd[4];
#pragma unroll
    for (int j = 0; j < 4; j++) {
        float a = 0.f, p = 0.f, ad = 0.f, pd = 0.f;
#pragma unroll
        for (int i = 0; i < 4; i++) {
            a  += Ws[i]     * Wa[i * 4 + j];
            p  += Ws[i]     * Wp[i * 4 + j];
            ad += Ws[4 + i] * Wa[i * 4 + j];
            pd += Ws[4 + i] * Wp[i * 4 + j];
        }
        vas[j] = a; vps[j] = p; vad[j] = ad; vpd[j] = pd;
    }
    float cas = 0.f, cps = 0.f, cad = 0.f, cpd = 0.f;
#pragma unroll
    for (int i = 0; i < 4; i++) {
        cas += Ws[i]     * ba[i];
        cps += Ws[i]     * bp[i];
        cad += Ws[4 + i] * ba[i];
        cpd += Ws[4 + i] * bp[i];
    }
    g_params.va_s = make_float4(vas[0], vas[1], vas[2], vas[3]);
    g_params.vp_s = make_float4(vps[0], vps[1], vps[2], vps[3]);
    g_params.va_d = make_float4(vad[0], vad[1], vad[2], vad[3]);
    g_params.vp_d = make_float4(vpd[0], vpd[1], vpd[2], vpd[3]);
#pragma unroll
    for (int t = 0; t < 4; t++) {
        int s = fsrc[t], d = fdst[t];
        g_params.fs[t] = s;
        g_params.fd[t] = d;
        g_params.c[t]  = bs[0] + (s ? cps : cas) + (d ? cpd : cad);
    }
}

__device__ __forceinline__ float dot4(float4 a, float4 b) {
    return a.x * b.x + a.y * b.y + a.z * b.z + a.w * b.w;
}

// --- node pass: 2 seq float4 reads, 2 seq float2 writes per node ---
__global__ void node_k(const float4* __restrict__ ax, const float4* __restrict__ px, int n)
{
    int i = blockIdx.x * blockDim.x + threadIdx.x;
    if (i >= n) return;
    float4 vas = g_params.va_s;
    float4 vps = g_params.vp_s;
    float4 vad = g_params.va_d;
    float4 vpd = g_params.vp_d;
    float4 a = ax[i];
    float4 p = px[i];
    g_SA[i] = make_float2(dot4(a, vas), dot4(p, vps));
    g_SD[i] = make_float2(dot4(a, vad), dot4(p, vpd));
}

// --- edge pass: vectorized x4, two random float2 gathers per edge ---
__device__ __forceinline__ float edge_score(int s, int d, int t,
                                            const float* sc, const int* sfs, const int* sfd)
{
    float2 sv = g_SA[s];
    float2 dv = g_SD[d];
    float va = sfs[t] ? sv.y : sv.x;
    float vb = sfd[t] ? dv.y : dv.x;
    return va + vb + sc[t];
}

__global__ void edge_k(const int* __restrict__ src, const int* __restrict__ dst,
                       const int* __restrict__ typ, float* __restrict__ out, int E)
{
    __shared__ float sc[4];
    __shared__ int   sfs[4];
    __shared__ int   sfd[4];
    if (threadIdx.x < 4) {
        sc[threadIdx.x]  = g_params.c[threadIdx.x];
        sfs[threadIdx.x] = g_params.fs[threadIdx.x];
        sfd[threadIdx.x] = g_params.fd[threadIdx.x];
    }
    __syncthreads();

    int i = blockIdx.x * blockDim.x + threadIdx.x;
    int base = i * 4;
    if (base + 3 < E) {
        int4 s4 = reinterpret_cast<const int4*>(src)[i];
        int4 d4 = reinterpret_cast<const int4*>(dst)[i];
        int4 t4 = reinterpret_cast<const int4*>(typ)[i];
        float4 o;
        o.x = edge_score(s4.x, d4.x, t4.x, sc, sfs, sfd);
        o.y = edge_score(s4.y, d4.y, t4.y, sc, sfs, sfd);
        o.z = edge_score(s4.z, d4.z, t4.z, sc, sfs, sfd);
        o.w = edge_score(s4.w, d4.w, t4.w, sc, sfs, sfd);
        reinterpret_cast<float4*>(out)[i] = o;
    } else if (base < E) {
        for (int e = base; e < E; e++)
            out[e] = edge_score(src[e], dst[e], typ[e], sc, sfs, sfd);
    }
}

extern "C" void kernel_launch(void* const* d_in, const int* in_sizes, int n_in,
                              void* d_out, int out_size)
{
    const float* author_x = (const float*)d_in[0];
    const float* paper_x  = (const float*)d_in[1];
    const int*   src      = (const int*)  d_in[2];
    const int*   dst      = (const int*)  d_in[3];
    const int*   typ      = (const int*)  d_in[4];
    const int*   fsrc     = (const int*)  d_in[5];
    const int*   fdst     = (const int*)  d_in[6];
    const float* Wa       = (const float*)d_in[7];
    const float* ba       = (const float*)d_in[8];
    const float* Wp       = (const float*)d_in[9];
    const float* bp       = (const float*)d_in[10];
    const float* Ws       = (const float*)d_in[11];
    const float* bs       = (const float*)d_in[12];

    int n_nodes = in_sizes[0] / 4;
    int E       = in_sizes[2];

    setup_k<<<1, 1>>>(Wa, ba, Wp, bp, Ws, bs, fsrc, fdst);

    int nb = (n_nodes + 255) / 256;
    node_k<<<nb, 256>>>((const float4*)author_x, (const float4*)paper_x, n_nodes);

    int quads = (E + 3) / 4;
    int eb = (quads + 255) / 256;
    edge_k<<<eb, 256>>>(src, dst, typ, (float*)d_out, E);
}

// round 3
// speedup vs baseline: 1.0019x; 1.0019x over previous
#include <cuda_runtime.h>

// ---------------------------------------------------------------------------
// TinyMixedHeteroLinkPredictor — round 3
//
// Algebra: fold the 8->1 scorer into the node encoders.
//   logit(e) = S[src].(fs[t]? p_s : a_s) + S[dst].(fd[t]? p_d : a_d) + c[t]
// where per node: S[n] = { ax[n].v_as, px[n].v_ps, ax[n].v_ad, px[n].v_pd }
// (v_* = Ws-half folded through Wa/Wp; biases folded into per-type c[t]).
//
// Two kernels only; the tiny weight folds are recomputed per block (L2-hit
// broadcast loads) instead of a serialized 1-thread setup kernel.
// ---------------------------------------------------------------------------

#define NMAX 2000000

__device__ float4 g_S[NMAX];   // per-node packed scores: {a_src, p_src, a_dst, p_dst}

__device__ __forceinline__ float dot4(float4 a, float4 b) {
    return a.x * b.x + a.y * b.y + a.z * b.z + a.w * b.w;
}

// --- node pass: fold weights per block, then 2 seq 16B reads + 1 seq 16B write/node
__global__ void node_k(const float4* __restrict__ ax, const float4* __restrict__ px,
                       const float* __restrict__ Wa, const float* __restrict__ Wp,
                       const float* __restrict__ Ws, int n)
{
    __shared__ float4 s_vas, s_vps, s_vad, s_vpd;
    if (threadIdx.x == 0) {
        float vas[4], vps[4], vad[4], vpd[4];
#pragma unroll
        for (int j = 0; j < 4; j++) {
            float a = 0.f, p = 0.f, ad = 0.f, pd = 0.f;
#pragma unroll
            for (int i = 0; i < 4; i++) {
                float wsi = Ws[i], wsd = Ws[4 + i];
                float wa = Wa[i * 4 + j], wp = Wp[i * 4 + j];
                a += wsi * wa;  p += wsi * wp;
                ad += wsd * wa; pd += wsd * wp;
            }
            vas[j] = a; vps[j] = p; vad[j] = ad; vpd[j] = pd;
        }
        s_vas = make_float4(vas[0], vas[1], vas[2], vas[3]);
        s_vps = make_float4(vps[0], vps[1], vps[2], vps[3]);
        s_vad = make_float4(vad[0], vad[1], vad[2], vad[3]);
        s_vpd = make_float4(vpd[0], vpd[1], vpd[2], vpd[3]);
    }
    __syncthreads();
    float4 vas = s_vas, vps = s_vps, vad = s_vad, vpd = s_vpd;

    int i = blockIdx.x * blockDim.x + threadIdx.x;
    if (i >= n) return;
    float4 a = ax[i];
    float4 p = px[i];
    g_S[i] = make_float4(dot4(a, vas), dot4(p, vps), dot4(a, vad), dot4(p, vpd));
}

// --- edge pass: 2 random 8B gathers per edge (the hard floor), x4 vectorized ---
__device__ __forceinline__ float edge_score(int s, int d, int t,
                                            const float* sc, const int* sfs, const int* sfd)
{
    // src gather: {a_src, p_src} = first 8B of g_S[s]
    const float2* ps = reinterpret_cast<const float2*>(&g_S[s]);
    // dst gather: {a_dst, p_dst} = second 8B of g_S[d]
    const float2* pd = reinterpret_cast<const float2*>(&g_S[d]) + 1;
    float2 sv = *ps;
    float2 dv = *pd;
    float va = sfs[t] ? sv.y : sv.x;
    float vb = sfd[t] ? dv.y : dv.x;
    return va + vb + sc[t];
}

__global__ void edge_k(const int* __restrict__ src, const int* __restrict__ dst,
                       const int* __restrict__ typ, float* __restrict__ out, int E,
                       const float* __restrict__ ba, const float* __restrict__ bp,
                       const float* __restrict__ Ws, const float* __restrict__ bs,
                       const int* __restrict__ fsrc, const int* __restrict__ fdst)
{
    __shared__ float sc[4];
    __shared__ int   sfs[4];
    __shared__ int   sfd[4];
    if (threadIdx.x == 0) {
        float cas = 0.f, cps = 0.f, cad = 0.f, cpd = 0.f;
#pragma unroll
        for (int i = 0; i < 4; i++) {
            cas += Ws[i]     * ba[i];
            cps += Ws[i]     * bp[i];
            cad += Ws[4 + i] * ba[i];
            cpd += Ws[4 + i] * bp[i];
        }
        float b0 = bs[0];
#pragma unroll
        for (int t = 0; t < 4; t++) {
            int s = fsrc[t], d = fdst[t];
            sfs[t] = s;
            sfd[t] = d;
            sc[t]  = b0 + (s ? cps : cas) + (d ? cpd : cad);
        }
    }
    __syncthreads();

    int i = blockIdx.x * blockDim.x + threadIdx.x;
    int base = i * 4;
    if (base + 3 < E) {
        int4 s4 = reinterpret_cast<const int4*>(src)[i];
        int4 d4 = reinterpret_cast<const int4*>(dst)[i];
        int4 t4 = reinterpret_cast<const int4*>(typ)[i];
        float4 o;
        o.x = edge_score(s4.x, d4.x, t4.x, sc, sfs, sfd);
        o.y = edge_score(s4.y, d4.y, t4.y, sc, sfs, sfd);
        o.z = edge_score(s4.z, d4.z, t4.z, sc, sfs, sfd);
        o.w = edge_score(s4.w, d4.w, t4.w, sc, sfs, sfd);
        reinterpret_cast<float4*>(out)[i] = o;
    } else if (base < E) {
        for (int e = base; e < E; e++)
            out[e] = edge_score(src[e], dst[e], typ[e], sc, sfs, sfd);
    }
}

extern "C" void kernel_launch(void* const* d_in, const int* in_sizes, int n_in,
                              void* d_out, int out_size)
{
    const float* author_x = (const float*)d_in[0];
    const float* paper_x  = (const float*)d_in[1];
    const int*   src      = (const int*)  d_in[2];
    const int*   dst      = (const int*)  d_in[3];
    const int*   typ      = (const int*)  d_in[4];
    const int*   fsrc     = (const int*)  d_in[5];
    const int*   fdst     = (const int*)  d_in[6];
    const float* Wa       = (const float*)d_in[7];
    const float* ba       = (const float*)d_in[8];
    const float* Wp       = (const float*)d_in[9];
    const float* bp       = (const float*)d_in[10];
    const float* Ws       = (const float*)d_in[11];
    const float* bs       = (const float*)d_in[12];

    int n_nodes = in_sizes[0] / 4;
    int E       = in_sizes[2];

    int nb = (n_nodes + 255) / 256;
    node_k<<<nb, 256>>>((const float4*)author_x, (const float4*)paper_x, Wa, Wp, Ws, n_nodes);

    int quads = (E + 3) / 4;
    int eb = (quads + 255) / 256;
    edge_k<<<eb, 256>>>(src, dst, typ, (float*)d_out, E, ba, bp, Ws, bs, fsrc, fdst);
}

// round 4
// speedup vs baseline: 1.0423x; 1.0403x over previous
#include <cuda_runtime.h>

// ---------------------------------------------------------------------------
// TinyMixedHeteroLinkPredictor — round 4: single fused kernel.
//
// Insight: the L1tex wavefront floor (2 random gathers/edge) is identical for
// 8B and 16B gathers (1 line + 1 sector per lane either way). So skip the
// node-encoding pass entirely: gather the raw float4 feature row from
// author_x or paper_x (selected by the relation-type flag) and fold the
// scorer-through-encoder dot product directly in the edge kernel.
//   logit(e) = feat_srcTab[src] . v_{tab,src} + feat_dstTab[dst] . v_{tab,dst} + c[t]
// Tiny weight folds recomputed per block by thread 0 (L2-broadcast loads).
// ---------------------------------------------------------------------------

__device__ __forceinline__ float dot4(float4 a, float4 b) {
    return a.x * b.x + a.y * b.y + a.z * b.z + a.w * b.w;
}

struct Folded {
    float4 vas, vps, vad, vpd;  // scorer halves folded through Wa/Wp
    float  c[4];                // per-type constant (biases + bs)
    int    fs[4], fd[4];        // per-type src/dst table flags
};

__global__ void __launch_bounds__(256) fused_k(
    const float4* __restrict__ ax, const float4* __restrict__ px,
    const int* __restrict__ src, const int* __restrict__ dst,
    const int* __restrict__ typ, float* __restrict__ out, int E,
    const float* __restrict__ Wa, const float* __restrict__ ba,
    const float* __restrict__ Wp, const float* __restrict__ bp,
    const float* __restrict__ Ws, const float* __restrict__ bs,
    const int* __restrict__ fsrc, const int* __restrict__ fdst)
{
    __shared__ Folded F;
    if (threadIdx.x == 0) {
        float vas[4], vps[4], vad[4], vpd[4];
#pragma unroll
        for (int j = 0; j < 4; j++) {
            float a = 0.f, p = 0.f, ad = 0.f, pd = 0.f;
#pragma unroll
            for (int i = 0; i < 4; i++) {
                float wsi = Ws[i], wsd = Ws[4 + i];
                float wa = Wa[i * 4 + j], wp = Wp[i * 4 + j];
                a  += wsi * wa;  p  += wsi * wp;
                ad += wsd * wa;  pd += wsd * wp;
            }
            vas[j] = a; vps[j] = p; vad[j] = ad; vpd[j] = pd;
        }
        F.vas = make_float4(vas[0], vas[1], vas[2], vas[3]);
        F.vps = make_float4(vps[0], vps[1], vps[2], vps[3]);
        F.vad = make_float4(vad[0], vad[1], vad[2], vad[3]);
        F.vpd = make_float4(vpd[0], vpd[1], vpd[2], vpd[3]);
        float cas = 0.f, cps = 0.f, cad = 0.f, cpd = 0.f;
#pragma unroll
        for (int i = 0; i < 4; i++) {
            cas += Ws[i]     * ba[i];
            cps += Ws[i]     * bp[i];
            cad += Ws[4 + i] * ba[i];
            cpd += Ws[4 + i] * bp[i];
        }
        float b0 = bs[0];
#pragma unroll
        for (int t = 0; t < 4; t++) {
            int s = fsrc[t], d = fdst[t];
            F.fs[t] = s;
            F.fd[t] = d;
            F.c[t]  = b0 + (s ? cps : cas) + (d ? cpd : cad);
        }
    }
    __syncthreads();

    // Keep folded vectors in registers (SEL-based select by flag).
    const float4 vas = F.vas, vps = F.vps, vad = F.vad, vpd = F.vpd;

    int i = blockIdx.x * blockDim.x + threadIdx.x;
    int base = i * 4;
    if (base + 3 < E) {
        int4 s4 = reinterpret_cast<const int4*>(src)[i];
        int4 d4 = reinterpret_cast<const int4*>(dst)[i];
        int4 t4 = reinterpret_cast<const int4*>(typ)[i];

        int se[4] = {s4.x, s4.y, s4.z, s4.w};
        int de[4] = {d4.x, d4.y, d4.z, d4.w};
        int te[4] = {t4.x, t4.y, t4.z, t4.w};

        // Issue all 8 gathers first for maximum MLP.
        float4 sf[4], df[4];
        int fsl[4], fdl[4];
#pragma unroll
        for (int k = 0; k < 4; k++) {
            fsl[k] = F.fs[te[k]];
            fdl[k] = F.fd[te[k]];
            const float4* sb = fsl[k] ? px : ax;
            const float4* db = fdl[k] ? px : ax;
            sf[k] = __ldg(&sb[se[k]]);
            df[k] = __ldg(&db[de[k]]);
        }

        float4 o;
        float r[4];
#pragma unroll
        for (int k = 0; k < 4; k++) {
            float4 vs = fsl[k] ? vps : vas;
            float4 vd = fdl[k] ? vpd : vad;
            r[k] = dot4(sf[k], vs) + dot4(df[k], vd) + F.c[te[k]];
        }
        o.x = r[0]; o.y = r[1]; o.z = r[2]; o.w = r[3];
        reinterpret_cast<float4*>(out)[i] = o;
    } else if (base < E) {
        for (int e = base; e < E; e++) {
            int t = typ[e];
            int s = src[e], d = dst[e];
            const float4* sb = F.fs[t] ? px : ax;
            const float4* db = F.fd[t] ? px : ax;
            float4 vs = F.fs[t] ? vps : vas;
            float4 vd = F.fd[t] ? vpd : vad;
            out[e] = dot4(__ldg(&sb[s]), vs) + dot4(__ldg(&db[d]), vd) + F.c[t];
        }
    }
}

extern "C" void kernel_launch(void* const* d_in, const int* in_sizes, int n_in,
                              void* d_out, int out_size)
{
    const float* author_x = (const float*)d_in[0];
    const float* paper_x  = (const float*)d_in[1];
    const int*   src      = (const int*)  d_in[2];
    const int*   dst      = (const int*)  d_in[3];
    const int*   typ      = (const int*)  d_in[4];
    const int*   fsrc     = (const int*)  d_in[5];
    const int*   fdst     = (const int*)  d_in[6];
    const float* Wa       = (const float*)d_in[7];
    const float* ba       = (const float*)d_in[8];
    const float* Wp       = (const float*)d_in[9];
    const float* bp       = (const float*)d_in[10];
    const float* Ws       = (const float*)d_in[11];
    const float* bs       = (const float*)d_in[12];

    int E = in_sizes[2];
    int quads = (E + 3) / 4;
    int eb = (quads + 255) / 256;
    fused_k<<<eb, 256>>>((const float4*)author_x, (const float4*)paper_x,
                         src, dst, typ, (float*)d_out, E,
                         Wa, ba, Wp, bp, Ws, bs, fsrc, fdst);
}

// round 5
// speedup vs baseline: 1.0590x; 1.0160x over previous
#include <cuda_runtime.h>

// ---------------------------------------------------------------------------
// TinyMixedHeteroLinkPredictor — round 5: fused kernel, cache-policy tuned.
//
//   logit(e) = feat_srcTab[src] . v_{tab,src} + feat_dstTab[dst] . v_{tab,dst} + c[t]
//
// vs round 4:
//  * index loads __ldcs / output __stcs (evict-first) -> streaming traffic no
//    longer evicts the 64 MB gather tables from L2 (L2 persists across graph
//    replays, so tables stay warm).
//  * gathers consumed in pairs (4 in flight) instead of 8 batched -> regs
//    48 -> ~40, occupancy 57% -> ~75% for gather-latency hiding.
// ---------------------------------------------------------------------------

__device__ __forceinline__ float dot4(float4 a, float4 b) {
    return a.x * b.x + a.y * b.y + a.z * b.z + a.w * b.w;
}

struct Folded {
    float4 vas, vps, vad, vpd;
    float  c[4];
    int    fs[4], fd[4];
};

__global__ void __launch_bounds__(256) fused_k(
    const float4* __restrict__ ax, const float4* __restrict__ px,
    const int* __restrict__ src, const int* __restrict__ dst,
    const int* __restrict__ typ, float* __restrict__ out, int E,
    const float* __restrict__ Wa, const float* __restrict__ ba,
    const float* __restrict__ Wp, const float* __restrict__ bp,
    const float* __restrict__ Ws, const float* __restrict__ bs,
    const int* __restrict__ fsrc, const int* __restrict__ fdst)
{
    __shared__ Folded F;
    if (threadIdx.x == 0) {
        float vas[4], vps[4], vad[4], vpd[4];
#pragma unroll
        for (int j = 0; j < 4; j++) {
            float a = 0.f, p = 0.f, ad = 0.f, pd = 0.f;
#pragma unroll
            for (int i = 0; i < 4; i++) {
                float wsi = Ws[i], wsd = Ws[4 + i];
                float wa = Wa[i * 4 + j], wp = Wp[i * 4 + j];
                a  += wsi * wa;  p  += wsi * wp;
                ad += wsd * wa;  pd += wsd * wp;
            }
            vas[j] = a; vps[j] = p; vad[j] = ad; vpd[j] = pd;
        }
        F.vas = make_float4(vas[0], vas[1], vas[2], vas[3]);
        F.vps = make_float4(vps[0], vps[1], vps[2], vps[3]);
        F.vad = make_float4(vad[0], vad[1], vad[2], vad[3]);
        F.vpd = make_float4(vpd[0], vpd[1], vpd[2], vpd[3]);
        float cas = 0.f, cps = 0.f, cad = 0.f, cpd = 0.f;
#pragma unroll
        for (int i = 0; i < 4; i++) {
            cas += Ws[i]     * ba[i];
            cps += Ws[i]     * bp[i];
            cad += Ws[4 + i] * ba[i];
            cpd += Ws[4 + i] * bp[i];
        }
        float b0 = bs[0];
#pragma unroll
        for (int t = 0; t < 4; t++) {
            int s = fsrc[t], d = fdst[t];
            F.fs[t] = s;
            F.fd[t] = d;
            F.c[t]  = b0 + (s ? cps : cas) + (d ? cpd : cad);
        }
    }
    __syncthreads();

    const float4 vas = F.vas, vps = F.vps, vad = F.vad, vpd = F.vpd;

    int i = blockIdx.x * blockDim.x + threadIdx.x;
    int base = i * 4;
    if (base + 3 < E) {
        // Streaming loads: evict-first so they don't displace the tables in L2.
        int4 s4 = __ldcs(reinterpret_cast<const int4*>(src) + i);
        int4 d4 = __ldcs(reinterpret_cast<const int4*>(dst) + i);
        int4 t4 = __ldcs(reinterpret_cast<const int4*>(typ) + i);

        int se[4] = {s4.x, s4.y, s4.z, s4.w};
        int de[4] = {d4.x, d4.y, d4.z, d4.w};
        int te[4] = {t4.x, t4.y, t4.z, t4.w};

        float r[4];
#pragma unroll
        for (int pair = 0; pair < 2; pair++) {
            int k0 = pair * 2, k1 = k0 + 1;
            int fs0 = F.fs[te[k0]], fd0 = F.fd[te[k0]];
            int fs1 = F.fs[te[k1]], fd1 = F.fd[te[k1]];
            // 4 gathers in flight
            float4 sf0 = __ldg((fs0 ? px : ax) + se[k0]);
            float4 df0 = __ldg((fd0 ? px : ax) + de[k0]);
            float4 sf1 = __ldg((fs1 ? px : ax) + se[k1]);
            float4 df1 = __ldg((fd1 ? px : ax) + de[k1]);
            r[k0] = dot4(sf0, fs0 ? vps : vas) + dot4(df0, fd0 ? vpd : vad) + F.c[te[k0]];
            r[k1] = dot4(sf1, fs1 ? vps : vas) + dot4(df1, fd1 ? vpd : vad) + F.c[te[k1]];
        }

        float4 o = make_float4(r[0], r[1], r[2], r[3]);
        __stcs(reinterpret_cast<float4*>(out) + i, o);
    } else if (base < E) {
        for (int e = base; e < E; e++) {
            int t = typ[e];
            int s = src[e], d = dst[e];
            const float4* sb = F.fs[t] ? px : ax;
            const float4* db = F.fd[t] ? px : ax;
            float4 vs = F.fs[t] ? vps : vas;
            float4 vd = F.fd[t] ? vpd : vad;
            out[e] = dot4(__ldg(&sb[s]), vs) + dot4(__ldg(&db[d]), vd) + F.c[t];
        }
    }
}

extern "C" void kernel_launch(void* const* d_in, const int* in_sizes, int n_in,
                              void* d_out, int out_size)
{
    const float* author_x = (const float*)d_in[0];
    const float* paper_x  = (const float*)d_in[1];
    const int*   src      = (const int*)  d_in[2];
    const int*   dst      = (const int*)  d_in[3];
    const int*   typ      = (const int*)  d_in[4];
    const int*   fsrc     = (const int*)  d_in[5];
    const int*   fdst     = (const int*)  d_in[6];
    const float* Wa       = (const float*)d_in[7];
    const float* ba       = (const float*)d_in[8];
    const float* Wp       = (const float*)d_in[9];
    const float* bp       = (const float*)d_in[10];
    const float* Ws       = (const float*)d_in[11];
    const float* bs       = (const float*)d_in[12];

    int E = in_sizes[2];
    int quads = (E + 3) / 4;
    int eb = (quads + 255) / 256;
    fused_k<<<eb, 256>>>((const float4*)author_x, (const float4*)paper_x,
                         src, dst, typ, (float*)d_out, E,
                         Wa, ba, Wp, bp, Ws, bs, fsrc, fdst);
}